// round 16
// baseline (speedup 1.0000x reference)
#include <cuda_runtime.h>
#include <cuda_fp16.h>
#include <cstdint>

#define BB 64
#define TT 256
#define CC 384
#define HH 6
#define DD 64
#define BT (BB*TT)         // 16384
#define NQKV (3*HH*DD)     // 1152
#define CPITCH 72          // fp16 elems per tile row (144B, 9-phase conflict-free)
#define TILE_E 9216        // elems per 128x64 tile (pitch 72)
#define TILE_B 18432       // bytes per tile
#define NCH 6              // K chunks (384/64)
#define NSTAGE 3

// proj GEMM small tiles (64 rows x 64 cols)
#define PT_E 4608          // elems per 64x64 tile
#define PT_B 9216          // bytes

// prep work partition (8 elems per thread)
#define XW (BT*CC/8)       // 786432
#define WTW (NQKV*CC/8)    // 55296
#define WPW (CC*CC/8)      // 18432

// attention smem layout (bytes). K pitch 72 fp16 (144B), Vt pitch 264 fp16 (528B)
#define AKH 0
#define AVH 36864
#define ASZ 70656

// ---------------- static scratch (tiled/pitched fp16 layouts) ----------------
__device__ __align__(128) __half g_Xh[(size_t)128*NCH*TILE_E];
__device__ __align__(128) __half g_Wth[(size_t)9*NCH*TILE_E];
__device__ __align__(128) __half g_Ath[(size_t)128*NCH*TILE_E];
__device__ __align__(128) __half g_Wph[(size_t)3*NCH*TILE_E];
__device__ __align__(128) __half g_Qh[(size_t)BB*HH*TT*72];
__device__ __align__(128) __half g_Kh[(size_t)BB*HH*TT*72];
__device__ __align__(128) __half g_Vth[(size_t)BB*HH*DD*264];

// ---------------- helpers ----------------
__device__ __forceinline__ void bulk_g2s(uint32_t dst, const void* src, uint32_t bytes,
                                         uint32_t mbar) {
    asm volatile("cp.async.bulk.shared::cluster.global.mbarrier::complete_tx::bytes "
                 "[%0], [%1], %2, [%3];"
                 :: "r"(dst), "l"(src), "r"(bytes), "r"(mbar) : "memory");
}
__device__ __forceinline__ void mbar_init(uint32_t mbar, uint32_t cnt) {
    asm volatile("mbarrier.init.shared.b64 [%0], %1;" :: "r"(mbar), "r"(cnt) : "memory");
}
__device__ __forceinline__ void mbar_expect(uint32_t mbar, uint32_t bytes) {
    asm volatile("mbarrier.arrive.expect_tx.shared.b64 _, [%0], %1;"
                 :: "r"(mbar), "r"(bytes) : "memory");
}
__device__ __forceinline__ void mbar_arrive(uint32_t mbar) {
    asm volatile("mbarrier.arrive.shared.b64 _, [%0];" :: "r"(mbar) : "memory");
}
__device__ __forceinline__ void mbar_wait(uint32_t mbar, uint32_t parity) {
    asm volatile("{\n\t.reg .pred P;\n\t"
                 "WL_%=:\n\t"
                 "mbarrier.try_wait.parity.acquire.cta.shared::cta.b64 P, [%0], %1, 0x989680;\n\t"
                 "@P bra WD_%=;\n\t"
                 "bra WL_%=;\n\t"
                 "WD_%=:\n\t}"
                 :: "r"(mbar), "r"(parity) : "memory");
}
__device__ __forceinline__ void fence_async() {
    asm volatile("fence.proxy.async.shared::cta;" ::: "memory");
}
__device__ __forceinline__ void mma_f16(float* c, const uint32_t* a, const uint32_t* b) {
    asm volatile("mma.sync.aligned.m16n8k16.row.col.f32.f16.f16.f32 "
                 "{%0,%1,%2,%3}, {%4,%5,%6,%7}, {%8,%9}, {%0,%1,%2,%3};"
                 : "+f"(c[0]), "+f"(c[1]), "+f"(c[2]), "+f"(c[3])
                 : "r"(a[0]), "r"(a[1]), "r"(a[2]), "r"(a[3]),
                   "r"(b[0]), "r"(b[1]));
}
__device__ __forceinline__ void ldm_x4(uint32_t* r, uint32_t addr) {
    asm volatile("ldmatrix.sync.aligned.m8n8.x4.shared.b16 {%0,%1,%2,%3}, [%4];"
                 : "=r"(r[0]), "=r"(r[1]), "=r"(r[2]), "=r"(r[3]) : "r"(addr));
}
__device__ __forceinline__ uint32_t packh2(float x, float y) {
    __half hx = __float2half_rn(x), hy = __float2half_rn(y);
    uint16_t ux = *(uint16_t*)&hx, uy = *(uint16_t*)&hy;
    return (uint32_t)ux | ((uint32_t)uy << 16);
}
__device__ __forceinline__ size_t tiled_idx(int m, int k) {   // 128-row blocks, 64-col chunks
    return ((size_t)(m >> 7) * NCH + (k >> 6)) * TILE_E + (m & 127) * CPITCH + (k & 63);
}

// ---------------- fused prep (all single fp16, tiled) ----------------
__global__ void prep(const float* __restrict__ x,
                     const float* __restrict__ Wq, const float* __restrict__ Wk,
                     const float* __restrict__ Wv, const float* __restrict__ Wp) {
    int g = blockIdx.x * blockDim.x + threadIdx.x;
    if (g < XW) {
        int i = g * 8;
        int m = i / CC, k = i % CC;
        float4 v0 = *(const float4*)(x + i);
        float4 v1 = *(const float4*)(x + i + 4);
        __half h[8];
        float vv[8] = {v0.x,v0.y,v0.z,v0.w,v1.x,v1.y,v1.z,v1.w};
        #pragma unroll
        for (int j = 0; j < 8; j++) h[j] = __float2half_rn(vv[j]);
        *(uint4*)(g_Xh + tiled_idx(m, k)) = *(uint4*)h;
    } else if (g < XW + WTW) {
        int idx8 = g - XW;
        int n = idx8 / (CC/8), c0 = (idx8 % (CC/8)) * 8;
        int proj = n / (HH * DD), r = n % (HH * DD);
        int h = r / DD, d = r % DD;
        const float* W = (proj == 0) ? Wq : (proj == 1) ? Wk : Wv;
        size_t o = tiled_idx(n, c0);
        #pragma unroll
        for (int cc = 0; cc < 8; cc++)
            g_Wth[o + cc] = __float2half_rn(W[((size_t)h * CC + c0 + cc) * DD + d]);
    } else if (g < XW + WTW + WPW) {
        int i = (g - XW - WTW) * 8;
        int n = i / CC, k = i % CC;
        float4 v0 = *(const float4*)(Wp + i);
        float4 v1 = *(const float4*)(Wp + i + 4);
        __half h[8];
        float vv[8] = {v0.x,v0.y,v0.z,v0.w,v1.x,v1.y,v1.z,v1.w};
        #pragma unroll
        for (int j = 0; j < 8; j++) h[j] = __float2half_rn(vv[j]);
        *(uint4*)(g_Wph + tiled_idx(n, k)) = *(uint4*)h;
    }
}

// ---------------------------------------------------------------------------
// QKV GEMM (128x128 tiles, 256 thr, occ2): A=X, B=Wt; emit Q,K (pitch 72),
// Vt (pitch 264), single fp16. BK=64, 3-stage bulk pipeline.
// ---------------------------------------------------------------------------
__global__ __launch_bounds__(256, 2) void gemm_qkv() {
    extern __shared__ __align__(128) char sm[];
    const int tid = threadIdx.x, lane = tid & 31, wid = tid >> 5;
    const int wm = wid & 3, wn = wid >> 2;
    const int lr = lane >> 2, lc = lane & 3;
    const int rb = blockIdx.y, cb = blockIdx.x;
    const int row0 = rb * 128, col0 = cb * 128;
    const uint32_t sbase = (uint32_t)__cvta_generic_to_shared(sm);
    const uint32_t barb = sbase + NSTAGE * 2 * TILE_B;

    uint32_t aoff[2];
    #pragma unroll
    for (int mt = 0; mt < 2; mt++)
        aoff[mt] = (uint32_t)(wm*32 + mt*16 + (lane & 15)) * CPITCH + ((lane >> 4) & 1) * 8;
    uint32_t boff[4];
    #pragma unroll
    for (int jj = 0; jj < 4; jj++)
        boff[jj] = (uint32_t)(wn*64 + jj*16 + ((lane >> 4) & 1)*8 + (lane & 7)) * CPITCH
                   + ((lane >> 3) & 1) * 8;

    if (tid == 0) {
        #pragma unroll
        for (int s = 0; s < NSTAGE; s++) {
            mbar_init(barb + s*8, 1);
            mbar_init(barb + (NSTAGE + s)*8, 8);
        }
    }
    __syncthreads();

    auto issue = [&](int s, int c) {
        uint32_t st = sbase + s * 2 * TILE_B;
        uint32_t mb = barb + s*8;
        fence_async();
        mbar_expect(mb, 2 * TILE_B);
        bulk_g2s(st,          g_Xh  + ((size_t)rb*NCH + c)*TILE_E, TILE_B, mb);
        bulk_g2s(st + TILE_B, g_Wth + ((size_t)cb*NCH + c)*TILE_E, TILE_B, mb);
    };

    float acc[2][8][4];
    #pragma unroll
    for (int i = 0; i < 2; i++)
        #pragma unroll
        for (int j = 0; j < 8; j++)
            #pragma unroll
            for (int r = 0; r < 4; r++) acc[i][j][r] = 0.f;

    if (tid == 0) { issue(0, 0); issue(1, 1); issue(2, 2); }

    for (int kc = 0; kc < NCH; kc++) {
        int buf = kc % NSTAGE;
        int par = (kc / NSTAGE) & 1;
        mbar_wait(barb + buf*8, par);

        const uint32_t sbuf = sbase + buf * 2 * TILE_B;
        #pragma unroll
        for (int ks = 0; ks < 4; ks++) {
            const uint32_t kb = ks * 16;
            uint32_t ah[2][4];
            #pragma unroll
            for (int mt = 0; mt < 2; mt++)
                ldm_x4(ah[mt], sbuf + (aoff[mt] + kb) * 2);
            #pragma unroll
            for (int jj = 0; jj < 4; jj++) {
                uint32_t bh4[4];
                ldm_x4(bh4, sbuf + TILE_B + (boff[jj] + kb) * 2);
                #pragma unroll
                for (int mt = 0; mt < 2; mt++) {
                    mma_f16(acc[mt][2*jj],   ah[mt], bh4);
                    mma_f16(acc[mt][2*jj+1], ah[mt], bh4 + 2);
                }
            }
        }
        if (lane == 0) mbar_arrive(barb + (NSTAGE + buf)*8);
        if (tid == 0 && kc + NSTAGE < NCH) {
            mbar_wait(barb + (NSTAGE + buf)*8, par);
            issue(buf, kc + NSTAGE);
        }
    }

    // epilogue -> Q/K/Vt
    #pragma unroll
    for (int i = 0; i < 2; i++) {
        int m0 = row0 + wm*32 + i*16 + lr;
        #pragma unroll
        for (int j = 0; j < 8; j++) {
            int nn = col0 + wn*64 + j*8 + lc*2;
            int proj = nn / (HH*DD);
            int rem  = nn % (HH*DD);
            int h = rem / DD, d = rem % DD;
            int b = m0 / TT, t = m0 % TT;
            int bh = b*HH + h;
            if (proj < 2) {
                __half* dst = (proj == 0) ? g_Qh : g_Kh;
                size_t o = ((size_t)bh*TT + t)*72 + d;
                *(uint32_t*)(dst + o)        = packh2(acc[i][j][0], acc[i][j][1]);
                *(uint32_t*)(dst + o + 8*72) = packh2(acc[i][j][2], acc[i][j][3]);
            } else {
                size_t o = ((size_t)bh*DD + d)*264 + t;
                g_Vth[o]           = __float2half_rn(acc[i][j][0]);
                g_Vth[o + 264]     = __float2half_rn(acc[i][j][1]);
                g_Vth[o + 8]       = __float2half_rn(acc[i][j][2]);
                g_Vth[o + 264 + 8] = __float2half_rn(acc[i][j][3]);
            }
        }
    }
}

// ---------------------------------------------------------------------------
// Projection GEMM, 64x64 tiles, 128 thr (4 warps 2m x 2n), 4 CTAs/SM.
// grid (6, 256). A = att tiled (64-row subtiles of 128-row blocks), B = Wp.
// ---------------------------------------------------------------------------
__global__ __launch_bounds__(128, 4) void gemm_proj(const float* __restrict__ bp,
                                                    float* __restrict__ outp) {
    extern __shared__ __align__(128) char sm[];
    const int tid = threadIdx.x, lane = tid & 31, wid = tid >> 5;
    const int wm = wid & 1, wn = wid >> 1;        // 2 x 2 warps
    const int lr = lane >> 2, lc = lane & 3;
    const int rb = blockIdx.y, cb = blockIdx.x;   // 64-row / 64-col blocks
    const int row0 = rb * 64, col0 = cb * 64;
    const uint32_t sbase = (uint32_t)__cvta_generic_to_shared(sm);
    const uint32_t barb = sbase + NSTAGE * 2 * PT_B;

    uint32_t aoff[2];
    #pragma unroll
    for (int mt = 0; mt < 2; mt++)
        aoff[mt] = (uint32_t)(wm*32 + mt*16 + (lane & 15)) * CPITCH + ((lane >> 4) & 1) * 8;
    uint32_t boff[2];
    #pragma unroll
    for (int jj = 0; jj < 2; jj++)
        boff[jj] = (uint32_t)(wn*32 + jj*16 + ((lane >> 4) & 1)*8 + (lane & 7)) * CPITCH
                   + ((lane >> 3) & 1) * 8;

    if (tid == 0) {
        #pragma unroll
        for (int s = 0; s < NSTAGE; s++) {
            mbar_init(barb + s*8, 1);
            mbar_init(barb + (NSTAGE + s)*8, 4);   // 4 warps
        }
    }
    __syncthreads();

    // 64-row subtile sources within 128-row tiled blocks (contiguous 9216B)
    const __half* Abase = g_Ath + ((size_t)(rb >> 1) * NCH) * TILE_E
                          + (size_t)(rb & 1) * 64 * CPITCH;
    const __half* Bbase = g_Wph + ((size_t)(cb >> 1) * NCH) * TILE_E
                          + (size_t)(cb & 1) * 64 * CPITCH;

    auto issue = [&](int s, int c) {
        uint32_t st = sbase + s * 2 * PT_B;
        uint32_t mb = barb + s*8;
        fence_async();
        mbar_expect(mb, 2 * PT_B);
        bulk_g2s(st,        Abase + (size_t)c*TILE_E, PT_B, mb);
        bulk_g2s(st + PT_B, Bbase + (size_t)c*TILE_E, PT_B, mb);
    };

    float acc[2][4][4];
    #pragma unroll
    for (int i = 0; i < 2; i++)
        #pragma unroll
        for (int j = 0; j < 4; j++)
            #pragma unroll
            for (int r = 0; r < 4; r++) acc[i][j][r] = 0.f;

    if (tid == 0) { issue(0, 0); issue(1, 1); issue(2, 2); }

    for (int kc = 0; kc < NCH; kc++) {
        int buf = kc % NSTAGE;
        int par = (kc / NSTAGE) & 1;
        mbar_wait(barb + buf*8, par);

        const uint32_t sbuf = sbase + buf * 2 * PT_B;
        #pragma unroll
        for (int ks = 0; ks < 4; ks++) {
            const uint32_t kb = ks * 16;
            uint32_t ah[2][4];
            #pragma unroll
            for (int mt = 0; mt < 2; mt++)
                ldm_x4(ah[mt], sbuf + (aoff[mt] + kb) * 2);
            #pragma unroll
            for (int jj = 0; jj < 2; jj++) {
                uint32_t bh4[4];
                ldm_x4(bh4, sbuf + PT_B + (boff[jj] + kb) * 2);
                #pragma unroll
                for (int mt = 0; mt < 2; mt++) {
                    mma_f16(acc[mt][2*jj],   ah[mt], bh4);
                    mma_f16(acc[mt][2*jj+1], ah[mt], bh4 + 2);
                }
            }
        }
        if (lane == 0) mbar_arrive(barb + (NSTAGE + buf)*8);
        if (tid == 0 && kc + NSTAGE < NCH) {
            mbar_wait(barb + (NSTAGE + buf)*8, par);
            issue(buf, kc + NSTAGE);
        }
    }

    // epilogue: +bias -> fp32 out
    #pragma unroll
    for (int i = 0; i < 2; i++) {
        int m0 = row0 + wm*32 + i*16 + lr;
        #pragma unroll
        for (int j = 0; j < 4; j++) {
            int nn = col0 + wn*32 + j*8 + lc*2;
            float2 bb = *(const float2*)(bp + nn);
            *(float2*)(outp + (size_t)m0 * CC + nn) =
                make_float2(acc[i][j][0] + bb.x, acc[i][j][1] + bb.y);
            *(float2*)(outp + (size_t)(m0 + 8) * CC + nn) =
                make_float2(acc[i][j][2] + bb.x, acc[i][j][3] + bb.y);
        }
    }
}

// ---------------------------------------------------------------------------
// HMMA flash attention, 1-product fp16. K+Vt bulk-staged in smem (70.7KB);
// Q fragments loaded directly from gmem (hoisted once per tile).
// 2 CTAs/SM. Load-balanced tiles j=w / j=15-w (5 chunks/warp).
// ---------------------------------------------------------------------------
__global__ __launch_bounds__(256, 2) void attn_flash() {
    extern __shared__ __align__(128) char sma[];
    const int bh = blockIdx.x;
    const int tid = threadIdx.x, lane = tid & 31, w = tid >> 5;
    const int lr = lane >> 2, lc = lane & 3;
    const uint32_t sb = (uint32_t)__cvta_generic_to_shared(sma);
    const uint32_t mb = sb + ASZ;

    if (tid == 0) {
        mbar_init(mb, 1);
        fence_async();
        mbar_expect(mb, ASZ);
        bulk_g2s(sb + AKH, g_Kh  + (size_t)bh*TT*72,  36864, mb);
        bulk_g2s(sb + AVH, g_Vth + (size_t)bh*DD*264, 33792, mb);
    }
    __syncthreads();
    mbar_wait(mb, 0);

    const int b = bh / HH, h = bh % HH;
    const __half* qg = g_Qh + (size_t)bh*TT*72;

    #pragma unroll
    for (int half = 0; half < 2; half++) {
        const int jt = half ? (15 - w) : w;
        const int rowbase = jt * 16;
        const int cnt = (jt >> 2) + 1;
        const int diagc = jt >> 2;

        uint32_t qh[4][4];
        #pragma unroll
        for (int ks = 0; ks < 4; ks++) {
            size_t off = (size_t)(rowbase + lr)*72 + ks*16 + lc*2;
            qh[ks][0] = *(const uint32_t*)(qg + off);
            qh[ks][1] = *(const uint32_t*)(qg + off + 8*72);
            qh[ks][2] = *(const uint32_t*)(qg + off + 8);
            qh[ks][3] = *(const uint32_t*)(qg + off + 8*72 + 8);
        }

        float O[8][4];
        #pragma unroll
        for (int j = 0; j < 8; j++)
            #pragma unroll
            for (int r = 0; r < 4; r++) O[j][r] = 0.f;
        float rowm[2] = {-1e30f, -1e30f};
        float rowl[2] = {0.f, 0.f};

        for (int c = 0; c < cnt; c++) {
            const int s0 = c * 64;
            float S[8][4];
            #pragma unroll
            for (int n = 0; n < 8; n++)
                #pragma unroll
                for (int r = 0; r < 4; r++) S[n][r] = 0.f;

            #pragma unroll
            for (int ks = 0; ks < 4; ks++) {
                #pragma unroll
                for (int n = 0; n < 8; n++) {
                    uint32_t off = (uint32_t)(s0 + n*8 + lr)*144 + (ks*16 + lc*2)*2;
                    uint32_t kb2[2];
                    kb2[0] = *(const uint32_t*)(sma + AKH + off);
                    kb2[1] = *(const uint32_t*)(sma + AKH + off + 16);
                    mma_f16(S[n], qh[ks], kb2);
                }
            }

            const bool diag = (c == diagc);
            const int trow = rowbase + lr;
            #pragma unroll
            for (int n = 0; n < 8; n++) {
                int scol = s0 + n*8 + lc*2;
                S[n][0] *= 0.125f; S[n][1] *= 0.125f;
                S[n][2] *= 0.125f; S[n][3] *= 0.125f;
                if (diag) {
                    if (scol     > trow)     S[n][0] = -1e30f;
                    if (scol + 1 > trow)     S[n][1] = -1e30f;
                    if (scol     > trow + 8) S[n][2] = -1e30f;
                    if (scol + 1 > trow + 8) S[n][3] = -1e30f;
                }
            }

            #pragma unroll
            for (int rg = 0; rg < 2; rg++) {
                float cm = -1e30f;
                #pragma unroll
                for (int n = 0; n < 8; n++) {
                    cm = fmaxf(cm, S[n][rg*2]);
                    cm = fmaxf(cm, S[n][rg*2+1]);
                }
                cm = fmaxf(cm, __shfl_xor_sync(0xffffffffu, cm, 1));
                cm = fmaxf(cm, __shfl_xor_sync(0xffffffffu, cm, 2));
                float mold = rowm[rg];
                float mn = fmaxf(mold, cm);
                float alpha = __expf(mold - mn);
                rowm[rg] = mn;
                float ls = 0.f;
                #pragma unroll
                for (int n = 0; n < 8; n++) {
                    float p0 = __expf(S[n][rg*2]   - mn);
                    float p1 = __expf(S[n][rg*2+1] - mn);
                    S[n][rg*2] = p0; S[n][rg*2+1] = p1;
                    ls += p0 + p1;
                }
                rowl[rg] = rowl[rg]*alpha + ls;
                #pragma unroll
                for (int j = 0; j < 8; j++) {
                    O[j][rg*2]   *= alpha;
                    O[j][rg*2+1] *= alpha;
                }
            }

            #pragma unroll
            for (int ks2 = 0; ks2 < 4; ks2++) {
                uint32_t ph[4];
                ph[0] = packh2(S[2*ks2][0],   S[2*ks2][1]);
                ph[1] = packh2(S[2*ks2][2],   S[2*ks2][3]);
                ph[2] = packh2(S[2*ks2+1][0], S[2*ks2+1][1]);
                ph[3] = packh2(S[2*ks2+1][2], S[2*ks2+1][3]);
                #pragma unroll
                for (int j = 0; j < 8; j++) {
                    uint32_t off = (uint32_t)(j*8 + lr)*528 + (s0 + ks2*16 + lc*2)*2;
                    uint32_t vb2[2];
                    vb2[0] = *(const uint32_t*)(sma + AVH + off);
                    vb2[1] = *(const uint32_t*)(sma + AVH + off + 16);
                    mma_f16(O[j], ph, vb2);
                }
            }
        }

        float linv0, linv1;
        {
            float lf = rowl[0];
            lf += __shfl_xor_sync(0xffffffffu, lf, 1);
            lf += __shfl_xor_sync(0xffffffffu, lf, 2);
            linv0 = 1.f / lf;
            lf = rowl[1];
            lf += __shfl_xor_sync(0xffffffffu, lf, 1);
            lf += __shfl_xor_sync(0xffffffffu, lf, 2);
            linv1 = 1.f / lf;
        }
        const int gm0 = b*TT + rowbase + lr;
        #pragma unroll
        for (int j = 0; j < 8; j++) {
            int n = h*DD + j*8 + lc*2;
            size_t o0 = tiled_idx(gm0, n);
            *(uint32_t*)(g_Ath + o0) = packh2(O[j][0]*linv0, O[j][1]*linv0);
            size_t o1 = tiled_idx(gm0 + 8, n);
            *(uint32_t*)(g_Ath + o1) = packh2(O[j][2]*linv1, O[j][3]*linv1);
        }
    }
}

// ---------------------------------------------------------------------------
extern "C" void kernel_launch(void* const* d_in, const int* in_sizes, int n_in,
                              void* d_out, int out_size) {
    const float* x  = (const float*)d_in[0];
    const float* Wq = (const float*)d_in[1];
    const float* Wk = (const float*)d_in[2];
    const float* Wv = (const float*)d_in[3];
    const float* Wp = (const float*)d_in[4];
    const float* bp = (const float*)d_in[5];
    float* out = (float*)d_out;

    prep<<<(XW + WTW + WPW) / 256, 256>>>(x, Wq, Wk, Wv, Wp);

    const int gsmem = NSTAGE * 2 * TILE_B + 48;   // 110640
    cudaFuncSetAttribute(gemm_qkv, cudaFuncAttributeMaxDynamicSharedMemorySize, gsmem);
    gemm_qkv<<<dim3(NQKV/128, BT/128), 256, gsmem>>>();

    cudaFuncSetAttribute(attn_flash, cudaFuncAttributeMaxDynamicSharedMemorySize, ASZ + 16);
    attn_flash<<<BB*HH, 256, ASZ + 16>>>();

    const int psmem = NSTAGE * 2 * PT_B + 48;     // 55344
    cudaFuncSetAttribute(gemm_proj, cudaFuncAttributeMaxDynamicSharedMemorySize, psmem);
    gemm_proj<<<dim3(CC/64, BT/64), 128, psmem>>>(bp, out);
}